// round 2
// baseline (speedup 1.0000x reference)
#include <cuda_runtime.h>
#include <cuda_bf16.h>
#include <cstdint>

#define B_SAMP 256
#define C_CLS  65536
#define D_DIM  2048
#define NCAM   8
#define CAP    12288
#define INV_TEMP 14.285714285714286f

#define TILE_N 64
#define TILE_M 32
#define TILE_K 64
#define GEMM_BLOCKS 1032

// ---------------- device scratch (no allocations allowed) ----------------
__device__ float g_sumexp[B_SAMP];
__device__ float g_pos[B_SAMP];
__device__ int   g_perm[NCAM * CAP];       // class ids grouped by camera, -1 padded to x64
__device__ int   g_samp[NCAM * B_SAMP];    // sample ids grouped by camera
__device__ int   g_samp_cnt[NCAM];
__device__ int   g_tile_base[NCAM + 1];
__device__ __align__(16) __nv_bfloat16 g_featb[B_SAMP * D_DIM];

// ---------------- helpers ----------------
__device__ __forceinline__ uint32_t smem_u32(const void* p) {
    return (uint32_t)__cvta_generic_to_shared(p);
}

__device__ __forceinline__ void ldsm_x4(uint32_t& r0, uint32_t& r1, uint32_t& r2, uint32_t& r3,
                                        uint32_t addr) {
    asm volatile("ldmatrix.sync.aligned.m8n8.x4.shared.b16 {%0,%1,%2,%3}, [%4];"
                 : "=r"(r0), "=r"(r1), "=r"(r2), "=r"(r3) : "r"(addr));
}

__device__ __forceinline__ void mma_bf16(float& c0, float& c1, float& c2, float& c3,
                                         uint32_t a0, uint32_t a1, uint32_t a2, uint32_t a3,
                                         uint32_t b0, uint32_t b1) {
    asm volatile(
        "mma.sync.aligned.m16n8k16.row.col.f32.bf16.bf16.f32 "
        "{%0,%1,%2,%3}, {%4,%5,%6,%7}, {%8,%9}, {%0,%1,%2,%3};"
        : "+f"(c0), "+f"(c1), "+f"(c2), "+f"(c3)
        : "r"(a0), "r"(a1), "r"(a2), "r"(a3), "r"(b0), "r"(b1));
}

__device__ __forceinline__ uint32_t bf2_bits(float a, float b) {
    unsigned short lo = __bfloat16_as_ushort(__float2bfloat16_rn(a));
    unsigned short hi = __bfloat16_as_ushort(__float2bfloat16_rn(b));
    return (uint32_t)lo | ((uint32_t)hi << 16);
}

// ---------------- features fp32 -> bf16 ----------------
__global__ void featconv_kernel(const float* __restrict__ f) {
    int i = blockIdx.x * blockDim.x + threadIdx.x;   // 131072 threads x float4
    float4 v = ((const float4*)f)[i];
    uint32_t lo = bf2_bits(v.x, v.y);
    uint32_t hi = bf2_bits(v.z, v.w);
    ((uint2*)g_featb)[i] = make_uint2(lo, hi);
}

// ---------------- prep: camera grouping + scratch reset ----------------
__global__ void prep_kernel(const int* __restrict__ class_camera,
                            const int* __restrict__ cams) {
    __shared__ int scnt[NCAM];
    __shared__ int ssnt[NCAM];
    int tid = threadIdx.x;  // 1024
    if (tid < NCAM) { scnt[tid] = 0; ssnt[tid] = 0; }
    if (tid < B_SAMP) { g_sumexp[tid] = 0.f; g_pos[tid] = 0.f; }
    __syncthreads();
    for (int j = tid; j < C_CLS; j += 1024) {
        int c = class_camera[j];
        int p = atomicAdd(&scnt[c], 1);
        g_perm[c * CAP + p] = j;
    }
    __syncthreads();
    if (tid < NCAM) {
        int cnt = scnt[tid];
        int pad = (cnt + 63) & ~63;
        for (int s = cnt; s < pad; s++) g_perm[tid * CAP + s] = -1;
    }
    __syncthreads();
    if (tid < B_SAMP) {
        int c = cams[tid];
        int p = atomicAdd(&ssnt[c], 1);
        g_samp[c * B_SAMP + p] = tid;
    }
    __syncthreads();
    if (tid == 0) {
        int tb = 0;
        for (int c = 0; c < NCAM; c++) {
            g_samp_cnt[c]  = ssnt[c];
            g_tile_base[c] = tb;
            tb += (scnt[c] + 63) >> 6;
        }
        g_tile_base[NCAM] = tb;
    }
}

// ---------------- fused GEMM + memory copy + exp reduce ----------------
// Block: 256 thr (8 warps). Tile: 32 samples x 64 classes, K streamed in 64-chunks.
// Warp w: mi = w&1 (m16), ni = w>>1 (n16). Each warp m16n16 via 2x m16n8k16.
__global__ __launch_bounds__(256) void gemm_kernel(const float* __restrict__ mem,
                                                   const int* __restrict__ labels,
                                                   float* __restrict__ out_mem) {
    int b = blockIdx.x;
    if (b >= g_tile_base[NCAM]) return;
    int cam = 0;
    while (b >= g_tile_base[cam + 1]) cam++;
    int tile = b - g_tile_base[cam];

    __shared__ int s_cls[TILE_N];
    __shared__ int s_samp[TILE_M];
    __shared__ int s_lab[TILE_M];
    __shared__ __align__(16) unsigned char smA[TILE_M * 128];  // 32 x 64 bf16, SW128
    __shared__ __align__(16) unsigned char smB[TILE_N * 128];  // 64 x 64 bf16, SW128

    int tid = threadIdx.x;
    int w = tid >> 5, L = tid & 31;
    int mi = w & 1, ni = w >> 1;

    if (tid < TILE_N) s_cls[tid] = g_perm[cam * CAP + tile * TILE_N + tid];
    int ncs = g_samp_cnt[cam];
    int nch = max(1, (ncs + TILE_M - 1) / TILE_M);

    uint32_t smA_u = smem_u32(smA);
    uint32_t smB_u = smem_u32(smB);

    for (int mc = 0; mc < nch; mc++) {
        if (tid < TILE_M) {
            int m = mc * TILE_M + tid;
            int s = (m < ncs) ? g_samp[cam * B_SAMP + m] : -1;
            s_samp[tid] = s;
            s_lab[tid]  = (s >= 0) ? labels[s] : -1;
        }
        __syncthreads();

        float acc[8];
#pragma unroll
        for (int i = 0; i < 8; i++) acc[i] = 0.f;

        for (int kt = 0; kt < D_DIM / TILE_K; kt++) {
            int k0 = kt * TILE_K;
            // ---- A tile: 32 rows x 64 bf16 from precomputed bf16 features
            {
                int r  = tid >> 3;
                int ch = tid & 7;
                int s = s_samp[r];
                uint4 v = make_uint4(0u, 0u, 0u, 0u);
                if (s >= 0)
                    v = *(const uint4*)(g_featb + (size_t)s * D_DIM + k0 + ch * 8);
                uint32_t o = (uint32_t)(r * 128 + ch * 16);
                o ^= ((o >> 3) & 0x70u);
                *(uint4*)(smA + o) = v;
            }
            // ---- B tile: 64 class rows x 64 f32 -> bf16, fused fp32 copy-out
            {
                int r  = tid & 63;
                int cc = tid >> 6;   // 0..3 -> floats [cc*16, cc*16+16)
                int cls = s_cls[r];
                float4 v0 = make_float4(0, 0, 0, 0), v1 = v0, v2 = v0, v3 = v0;
                if (cls >= 0) {
                    const float* src = mem + (size_t)cls * D_DIM + k0 + cc * 16;
                    v0 = *(const float4*)(src + 0);
                    v1 = *(const float4*)(src + 4);
                    v2 = *(const float4*)(src + 8);
                    v3 = *(const float4*)(src + 12);
                    if (mc == 0) {
                        float* o = out_mem + (size_t)cls * D_DIM + k0 + cc * 16;
                        o[0]=v0.x; o[1]=v0.y; o[2]=v0.z; o[3]=v0.w;
                        o[4]=v1.x; o[5]=v1.y; o[6]=v1.z; o[7]=v1.w;
                        o[8]=v2.x; o[9]=v2.y; o[10]=v2.z; o[11]=v2.w;
                        o[12]=v3.x; o[13]=v3.y; o[14]=v3.z; o[15]=v3.w;
                    }
                }
                uint4 p0, p1;
                p0.x = bf2_bits(v0.x, v0.y); p0.y = bf2_bits(v0.z, v0.w);
                p0.z = bf2_bits(v1.x, v1.y); p0.w = bf2_bits(v1.z, v1.w);
                p1.x = bf2_bits(v2.x, v2.y); p1.y = bf2_bits(v2.z, v2.w);
                p1.z = bf2_bits(v3.x, v3.y); p1.w = bf2_bits(v3.z, v3.w);
                uint32_t o0 = (uint32_t)(r * 128 + cc * 32);
                uint32_t o1 = o0 + 16;
                o0 ^= ((o0 >> 3) & 0x70u);
                o1 ^= ((o1 >> 3) & 0x70u);
                *(uint4*)(smB + o0) = p0;
                *(uint4*)(smB + o1) = p1;
            }
            __syncthreads();

            uint32_t arow = (uint32_t)(mi * 16 + (L & 15));
            uint32_t brow = (uint32_t)(ni * 16 + (L & 15));
            uint32_t kh   = (uint32_t)(L >> 4) * 16u;
#pragma unroll
            for (int ks = 0; ks < 4; ks++) {
                uint32_t acol = (uint32_t)(ks * 32) + kh;
                uint32_t ao = arow * 128 + acol; ao ^= ((ao >> 3) & 0x70u);
                uint32_t bo = brow * 128 + acol; bo ^= ((bo >> 3) & 0x70u);
                uint32_t a0, a1, a2, a3, b0, b1, b2, b3;
                ldsm_x4(a0, a1, a2, a3, smA_u + ao);
                ldsm_x4(b0, b1, b2, b3, smB_u + bo);
                mma_bf16(acc[0], acc[1], acc[2], acc[3], a0, a1, a2, a3, b0, b2);
                mma_bf16(acc[4], acc[5], acc[6], acc[7], a0, a1, a2, a3, b1, b3);
            }
            __syncthreads();
        }

        // ---- epilogue: scale, exp with validity mask, pos capture, row reduce
        {
            int rlo = mi * 16 + (L >> 2);
            int rhi = rlo + 8;
            int c0  = ni * 16 + (L & 3) * 2;
            int slo_s = s_samp[rlo], shi_s = s_samp[rhi];
            int llo = s_lab[rlo],    lhi = s_lab[rhi];
            float slo = 0.f, shi = 0.f;
#pragma unroll
            for (int e = 0; e < 8; e++) {
                // e -> (row, col): 0:(lo,c0) 1:(lo,c0+1) 2:(hi,c0) 3:(hi,c0+1)
                //                  4:(lo,c0+8) 5:(lo,c0+9) 6:(hi,c0+8) 7:(hi,c0+9)
                int hi_row = (e >> 1) & 1;
                int col = c0 + (e & 1) + ((e >> 2) << 3);
                int cls = s_cls[col];
                int s   = hi_row ? shi_s : slo_s;
                if (cls >= 0 && s >= 0) {
                    float val = acc[e] * INV_TEMP;
                    float ev = __expf(val);
                    if (hi_row) shi += ev; else slo += ev;
                    int lab = hi_row ? lhi : llo;
                    if (cls == lab) g_pos[s] = val;
                }
            }
            slo += __shfl_xor_sync(0xffffffffu, slo, 1);
            slo += __shfl_xor_sync(0xffffffffu, slo, 2);
            shi += __shfl_xor_sync(0xffffffffu, shi, 1);
            shi += __shfl_xor_sync(0xffffffffu, shi, 2);
            if ((L & 3) == 0) {
                if (slo_s >= 0) atomicAdd(&g_sumexp[slo_s], slo);
                if (shi_s >= 0) atomicAdd(&g_sumexp[shi_s], shi);
            }
        }
        __syncthreads();
    }
}

// ---------------- sequential EMA per label chain ----------------
__global__ __launch_bounds__(256) void ema_kernel(const float* __restrict__ mem,
                                                  const float* __restrict__ feat,
                                                  const int* __restrict__ labels,
                                                  float* __restrict__ out_mem) {
    int b = blockIdx.x;
    int y = labels[b];
    for (int j = b + 1; j < B_SAMP; j++)
        if (labels[j] == y) return;          // only last occurrence owns the chain
    int t = threadIdx.x;
    float r[8];
    const float* m = mem + (size_t)y * D_DIM;
#pragma unroll
    for (int i = 0; i < 8; i++) r[i] = m[t + i * 256];
    __shared__ float red[256];
    for (int j = 0; j < B_SAMP; j++) {
        if (labels[j] != y) continue;
        const float* x = feat + (size_t)j * D_DIM;
        float ss = 0.f;
#pragma unroll
        for (int i = 0; i < 8; i++) {
            r[i] = 0.2f * r[i] + 0.8f * x[t + i * 256];
            ss += r[i] * r[i];
        }
        red[t] = ss;
        __syncthreads();
        for (int s = 128; s > 0; s >>= 1) {
            if (t < s) red[t] += red[t + s];
            __syncthreads();
        }
        float rinv = rsqrtf(red[0]);
        __syncthreads();
#pragma unroll
        for (int i = 0; i < 8; i++) r[i] *= rinv;
    }
    float* o = out_mem + (size_t)y * D_DIM;
#pragma unroll
    for (int i = 0; i < 8; i++) o[t + i * 256] = r[i];
}

// ---------------- loss finalize ----------------
__global__ void loss_kernel(const int* __restrict__ cams, float* __restrict__ out) {
    __shared__ float red[256];
    int t = threadIdx.x;
    float v = (logf(g_sumexp[t]) - g_pos[t]) / (float)g_samp_cnt[cams[t]];
    red[t] = v;
    __syncthreads();
    for (int s = 128; s > 0; s >>= 1) {
        if (t < s) red[t] += red[t + s];
        __syncthreads();
    }
    if (t == 0) out[0] = red[0];
}

extern "C" void kernel_launch(void* const* d_in, const int* in_sizes, int n_in,
                              void* d_out, int out_size) {
    const float* features     = (const float*)d_in[0];
    const int*   labels       = (const int*)d_in[1];
    const int*   cams         = (const int*)d_in[2];
    const float* class_memory = (const float*)d_in[3];
    const int*   class_camera = (const int*)d_in[4];
    float* out = (float*)d_out;          // [0] = loss, [1..] = new_memory
    float* out_mem = out + 1;

    featconv_kernel<<<512, 256>>>(features);
    prep_kernel<<<1, 1024>>>(class_camera, cams);
    gemm_kernel<<<GEMM_BLOCKS, 256>>>(class_memory, labels, out_mem);
    ema_kernel<<<B_SAMP, 256>>>(class_memory, features, labels, out_mem);
    loss_kernel<<<1, 256>>>(cams, out);
}

// round 3
// speedup vs baseline: 3.8844x; 3.8844x over previous
#include <cuda_runtime.h>
#include <cuda_bf16.h>
#include <cstdint>

#define B_SAMP 256
#define C_CLS  65536
#define D_DIM  2048
#define NCAM   8
#define CAP    12288
#define INV_TEMP 14.285714285714286f

#define TILE_N 64
#define TILE_M 32
#define TILE_K 64
#define GEMM_BLOCKS 1032
#define PREP_BLOCKS 64

// ---------------- device scratch ----------------
__device__ float g_sumexp[B_SAMP];
__device__ float g_pos[B_SAMP];
__device__ int   g_perm[NCAM * CAP];
__device__ int   g_samp[NCAM * B_SAMP];
__device__ int   g_samp_cnt[NCAM];
__device__ int   g_tile_base[NCAM + 1];
__device__ int   g_blkcnt[PREP_BLOCKS * NCAM];
__device__ int   g_blkbase[PREP_BLOCKS * NCAM];
__device__ __align__(16) __nv_bfloat16 g_featb[B_SAMP * D_DIM];

// ---------------- helpers ----------------
__device__ __forceinline__ uint32_t smem_u32(const void* p) {
    return (uint32_t)__cvta_generic_to_shared(p);
}
__device__ __forceinline__ void ldsm_x4(uint32_t& r0, uint32_t& r1, uint32_t& r2, uint32_t& r3,
                                        uint32_t addr) {
    asm volatile("ldmatrix.sync.aligned.m8n8.x4.shared.b16 {%0,%1,%2,%3}, [%4];"
                 : "=r"(r0), "=r"(r1), "=r"(r2), "=r"(r3) : "r"(addr));
}
__device__ __forceinline__ void mma_bf16(float& c0, float& c1, float& c2, float& c3,
                                         uint32_t a0, uint32_t a1, uint32_t a2, uint32_t a3,
                                         uint32_t b0, uint32_t b1) {
    asm volatile(
        "mma.sync.aligned.m16n8k16.row.col.f32.bf16.bf16.f32 "
        "{%0,%1,%2,%3}, {%4,%5,%6,%7}, {%8,%9}, {%0,%1,%2,%3};"
        : "+f"(c0), "+f"(c1), "+f"(c2), "+f"(c3)
        : "r"(a0), "r"(a1), "r"(a2), "r"(a3), "r"(b0), "r"(b1));
}
__device__ __forceinline__ uint32_t bf2_bits(float a, float b) {
    unsigned short lo = __bfloat16_as_ushort(__float2bfloat16_rn(a));
    unsigned short hi = __bfloat16_as_ushort(__float2bfloat16_rn(b));
    return (uint32_t)lo | ((uint32_t)hi << 16);
}
__device__ __forceinline__ uint32_t sw128(uint32_t o) { return o ^ ((o >> 3) & 0x70u); }

// ---------------- features fp32 -> bf16 ----------------
__global__ void featconv_kernel(const float* __restrict__ f) {
    int i = blockIdx.x * blockDim.x + threadIdx.x;
    float4 v = ((const float4*)f)[i];
    ((uint2*)g_featb)[i] = make_uint2(bf2_bits(v.x, v.y), bf2_bits(v.z, v.w));
}

// ---------------- prep 1: per-block camera histogram ----------------
__global__ void prep1_kernel(const int* __restrict__ class_camera) {
    __shared__ int h[NCAM];
    int tid = threadIdx.x;                 // 256
    if (tid < NCAM) h[tid] = 0;
    __syncthreads();
    int4 c4 = ((const int4*)class_camera)[blockIdx.x * 256 + tid];
    atomicAdd(&h[c4.x], 1); atomicAdd(&h[c4.y], 1);
    atomicAdd(&h[c4.z], 1); atomicAdd(&h[c4.w], 1);
    __syncthreads();
    if (tid < NCAM) g_blkcnt[blockIdx.x * NCAM + tid] = h[tid];
}

// ---------------- prep 2: scan + sample grouping + tile bases ----------------
__global__ void prep2_kernel(const int* __restrict__ cams) {
    __shared__ int scnt[NCAM];
    __shared__ int ssnt[NCAM];
    int tid = threadIdx.x;                 // 256
    if (tid < B_SAMP) { g_sumexp[tid] = 0.f; g_pos[tid] = 0.f; }
    if (tid < NCAM) ssnt[tid] = 0;
    if (tid < NCAM) {
        int base = 0;
        for (int b = 0; b < PREP_BLOCKS; b++) {
            g_blkbase[b * NCAM + tid] = base;
            base += g_blkcnt[b * NCAM + tid];
        }
        scnt[tid] = base;
        int pad = (base + 63) & ~63;
        for (int s = base; s < pad; s++) g_perm[tid * CAP + s] = -1;
    }
    __syncthreads();
    {
        int c = cams[tid];
        int p = atomicAdd(&ssnt[c], 1);
        g_samp[c * B_SAMP + p] = tid;
    }
    __syncthreads();
    if (tid < NCAM) g_samp_cnt[tid] = ssnt[tid];
    if (tid == 0) {
        int tb = 0;
        for (int c = 0; c < NCAM; c++) {
            g_tile_base[c] = tb;
            tb += (scnt[c] + 63) >> 6;
        }
        g_tile_base[NCAM] = tb;
    }
}

// ---------------- prep 3: scatter class ids by camera ----------------
__global__ void prep3_kernel(const int* __restrict__ class_camera) {
    __shared__ int off[NCAM];
    int tid = threadIdx.x;
    if (tid < NCAM) off[tid] = g_blkbase[blockIdx.x * NCAM + tid];
    __syncthreads();
    int base = blockIdx.x * 1024 + tid * 4;
    int4 c4 = ((const int4*)class_camera)[blockIdx.x * 256 + tid];
    int p;
    p = atomicAdd(&off[c4.x], 1); g_perm[c4.x * CAP + p] = base + 0;
    p = atomicAdd(&off[c4.y], 1); g_perm[c4.y * CAP + p] = base + 1;
    p = atomicAdd(&off[c4.z], 1); g_perm[c4.z * CAP + p] = base + 2;
    p = atomicAdd(&off[c4.w], 1); g_perm[c4.w * CAP + p] = base + 3;
}

// ---------------- fused GEMM + memory copy + exp reduce ----------------
__global__ __launch_bounds__(256) void gemm_kernel(const float* __restrict__ mem,
                                                   const int* __restrict__ labels,
                                                   float* __restrict__ out_mem) {
    int b = blockIdx.x;
    if (b >= g_tile_base[NCAM]) return;
    int cam = 0;
    while (b >= g_tile_base[cam + 1]) cam++;
    int tile = b - g_tile_base[cam];

    __shared__ int s_cls[TILE_N];
    __shared__ int s_samp[TILE_M];
    __shared__ int s_lab[TILE_M];
    __shared__ __align__(16) unsigned char smA[2][TILE_M * 128];
    __shared__ __align__(16) unsigned char smB[2][TILE_N * 128];

    int tid = threadIdx.x;
    int w = tid >> 5, L = tid & 31;
    int mi = w & 1, ni = w >> 1;

    if (tid < TILE_N) s_cls[tid] = g_perm[cam * CAP + tile * TILE_N + tid];
    int ncs = g_samp_cnt[cam];
    int nch = max(1, (ncs + TILE_M - 1) / TILE_M);
    __syncthreads();

    // ---- per-thread B mapping: round r covers rows [r*16, r*16+16),
    //      16 lanes per row, each lane a contiguous float4 (coalesced).
    const float* bsrc[4];
    float*       bdst[4];
    uint32_t     bso[4];
    {
        int lane16 = tid & 15;
#pragma unroll
        for (int r = 0; r < 4; r++) {
            int row = r * 16 + (tid >> 4);
            int cls = s_cls[row];
            bsrc[r] = (cls >= 0) ? mem + (size_t)cls * D_DIM + lane16 * 4 : nullptr;
            bdst[r] = (cls >= 0) ? out_mem + (size_t)cls * D_DIM + lane16 * 4 : nullptr;
            bso[r] = sw128((uint32_t)(row * 128 + lane16 * 8));
        }
    }
    // ---- A mapping: row = tid>>3 (32 rows), 8 lanes/row of 16B (coalesced)
    int arow = tid >> 3;
    int ach  = tid & 7;
    uint32_t aso = sw128((uint32_t)(arow * 128 + ach * 16));

    uint32_t smA_u[2] = { smem_u32(smA[0]), smem_u32(smA[1]) };
    uint32_t smB_u[2] = { smem_u32(smB[0]), smem_u32(smB[1]) };

    for (int mc = 0; mc < nch; mc++) {
        if (tid < TILE_M) {
            int m = mc * TILE_M + tid;
            int s = (m < ncs) ? g_samp[cam * B_SAMP + m] : -1;
            s_samp[tid] = s;
            s_lab[tid]  = (s >= 0) ? labels[s] : -1;
        }
        __syncthreads();
        int samp = s_samp[arow];
        const __nv_bfloat16* asrc = (samp >= 0)
            ? g_featb + (size_t)samp * D_DIM + ach * 8 : nullptr;

        float acc[8];
#pragma unroll
        for (int i = 0; i < 8; i++) acc[i] = 0.f;

        // prefetch kt = 0
        float4 vb[4];
        uint4  va;
#pragma unroll
        for (int r = 0; r < 4; r++)
            vb[r] = bsrc[r] ? *(const float4*)(bsrc[r]) : make_float4(0, 0, 0, 0);
        va = asrc ? *(const uint4*)(asrc) : make_uint4(0, 0, 0, 0);

        bool do_copy = (mc == 0);
        for (int kt = 0; kt < D_DIM / TILE_K; kt++) {
            int buf = kt & 1;
            // store current regs to smem (+ fused fp32 copy-out)
            *(uint4*)(smA[buf] + aso) = va;
#pragma unroll
            for (int r = 0; r < 4; r++) {
                uint2 p;
                p.x = bf2_bits(vb[r].x, vb[r].y);
                p.y = bf2_bits(vb[r].z, vb[r].w);
                *(uint2*)(smB[buf] + bso[r]) = p;
                if (do_copy && bdst[r]) {
                    float* o = bdst[r] + kt * TILE_K;
                    o[0] = vb[r].x; o[1] = vb[r].y; o[2] = vb[r].z; o[3] = vb[r].w;
                }
            }
            __syncthreads();
            // prefetch kt+1
            if (kt < D_DIM / TILE_K - 1) {
                int ko = (kt + 1) * TILE_K;
#pragma unroll
                for (int r = 0; r < 4; r++)
                    vb[r] = bsrc[r] ? *(const float4*)(bsrc[r] + ko)
                                    : make_float4(0, 0, 0, 0);
                va = asrc ? *(const uint4*)(asrc + ko) : make_uint4(0, 0, 0, 0);
            }
            // mma on smem[buf]
            {
                uint32_t arw = (uint32_t)(mi * 16 + (L & 15));
                uint32_t brw = (uint32_t)(ni * 16 + (L & 15));
                uint32_t kh  = (uint32_t)(L >> 4) * 16u;
#pragma unroll
                for (int ks = 0; ks < 4; ks++) {
                    uint32_t acol = (uint32_t)(ks * 32) + kh;
                    uint32_t ao = sw128(arw * 128 + acol);
                    uint32_t bo = sw128(brw * 128 + acol);
                    uint32_t a0, a1, a2, a3, b0, b1, b2, b3;
                    ldsm_x4(a0, a1, a2, a3, smA_u[buf] + ao);
                    ldsm_x4(b0, b1, b2, b3, smB_u[buf] + bo);
                    mma_bf16(acc[0], acc[1], acc[2], acc[3], a0, a1, a2, a3, b0, b2);
                    mma_bf16(acc[4], acc[5], acc[6], acc[7], a0, a1, a2, a3, b1, b3);
                }
            }
        }

        // ---- epilogue (validated in round 2)
        {
            int rlo = mi * 16 + (L >> 2);
            int rhi = rlo + 8;
            int c0  = ni * 16 + (L & 3) * 2;
            int slo_s = s_samp[rlo], shi_s = s_samp[rhi];
            int llo = s_lab[rlo],    lhi = s_lab[rhi];
            float slo = 0.f, shi = 0.f;
#pragma unroll
            for (int e = 0; e < 8; e++) {
                int hi_row = (e >> 1) & 1;
                int col = c0 + (e & 1) + ((e >> 2) << 3);
                int cls = s_cls[col];
                int s   = hi_row ? shi_s : slo_s;
                if (cls >= 0 && s >= 0) {
                    float val = acc[e] * INV_TEMP;
                    float ev = __expf(val);
                    if (hi_row) shi += ev; else slo += ev;
                    int lab = hi_row ? lhi : llo;
                    if (cls == lab) g_pos[s] = val;
                }
            }
            slo += __shfl_xor_sync(0xffffffffu, slo, 1);
            slo += __shfl_xor_sync(0xffffffffu, slo, 2);
            shi += __shfl_xor_sync(0xffffffffu, shi, 1);
            shi += __shfl_xor_sync(0xffffffffu, shi, 2);
            if ((L & 3) == 0) {
                if (slo_s >= 0) atomicAdd(&g_sumexp[slo_s], slo);
                if (shi_s >= 0) atomicAdd(&g_sumexp[shi_s], shi);
            }
        }
        __syncthreads();
    }
}

// ---------------- sequential EMA per label chain ----------------
__global__ __launch_bounds__(256) void ema_kernel(const float* __restrict__ mem,
                                                  const float* __restrict__ feat,
                                                  const int* __restrict__ labels,
                                                  float* __restrict__ out_mem) {
    int b = blockIdx.x;
    int y = labels[b];
    for (int j = b + 1; j < B_SAMP; j++)
        if (labels[j] == y) return;          // only last occurrence owns the chain
    int t = threadIdx.x;
    int lane = t & 31, wid = t >> 5;
    float r[8];
    const float* m = mem + (size_t)y * D_DIM;
#pragma unroll
    for (int i = 0; i < 8; i++) r[i] = m[t + i * 256];
    __shared__ float wsum[8];
    for (int j = 0; j < B_SAMP; j++) {
        if (labels[j] != y) continue;
        const float* x = feat + (size_t)j * D_DIM;
        float ss = 0.f;
#pragma unroll
        for (int i = 0; i < 8; i++) {
            r[i] = 0.2f * r[i] + 0.8f * x[t + i * 256];
            ss += r[i] * r[i];
        }
#pragma unroll
        for (int o = 16; o > 0; o >>= 1) ss += __shfl_xor_sync(0xffffffffu, ss, o);
        if (lane == 0) wsum[wid] = ss;
        __syncthreads();
        float tot = wsum[0] + wsum[1] + wsum[2] + wsum[3]
                  + wsum[4] + wsum[5] + wsum[6] + wsum[7];
        float rinv = rsqrtf(tot);
        __syncthreads();
#pragma unroll
        for (int i = 0; i < 8; i++) r[i] *= rinv;
    }
    float* o = out_mem + (size_t)y * D_DIM;
#pragma unroll
    for (int i = 0; i < 8; i++) o[t + i * 256] = r[i];
}

// ---------------- loss finalize ----------------
__global__ void loss_kernel(const int* __restrict__ cams, float* __restrict__ out) {
    __shared__ float red[256];
    int t = threadIdx.x;
    float v = (logf(g_sumexp[t]) - g_pos[t]) / (float)g_samp_cnt[cams[t]];
    red[t] = v;
    __syncthreads();
    for (int s = 128; s > 0; s >>= 1) {
        if (t < s) red[t] += red[t + s];
        __syncthreads();
    }
    if (t == 0) out[0] = red[0];
}

extern "C" void kernel_launch(void* const* d_in, const int* in_sizes, int n_in,
                              void* d_out, int out_size) {
    const float* features     = (const float*)d_in[0];
    const int*   labels       = (const int*)d_in[1];
    const int*   cams         = (const int*)d_in[2];
    const float* class_memory = (const float*)d_in[3];
    const int*   class_camera = (const int*)d_in[4];
    float* out = (float*)d_out;          // [0] = loss, [1..] = new_memory
    float* out_mem = out + 1;

    featconv_kernel<<<512, 256>>>(features);
    prep1_kernel<<<PREP_BLOCKS, 256>>>(class_camera);
    prep2_kernel<<<1, 256>>>(cams);
    prep3_kernel<<<PREP_BLOCKS, 256>>>(class_camera);
    gemm_kernel<<<GEMM_BLOCKS, 256>>>(class_memory, labels, out_mem);
    ema_kernel<<<B_SAMP, 256>>>(class_memory, features, labels, out_mem);
    loss_kernel<<<1, 256>>>(cams, out);
}